// round 15
// baseline (speedup 1.0000x reference)
#include <cuda_runtime.h>
#include <cuda_bf16.h>

// ObjectLoss: segment-normalized weighted MSE.
//   valid = reconstructable > 0, xi = arctanh(beta)^2
//   num[p] = sum mse_i*xi_i over valid hits of pid p; den[p] = sum xi_i
//   out = mean_{p=1..P-1} num[p]/den[p]
//
// Single fused kernel (atomic accumulate + last-block reduce) preceded by one
// memset node. Node overhead was ~40% of round-13's 25 us.

#define P_SEGS 50000
#define TPB 1024

struct Acc {
    float num[P_SEGS];
    float den[P_SEGS];
    unsigned int ticket;
};
__device__ Acc g_acc;

__global__ __launch_bounds__(TPB) void fused_kernel(
    const float*  __restrict__ beta,
    const float4* __restrict__ pred,
    const int*    __restrict__ pid,
    const float4* __restrict__ tp,
    const int*    __restrict__ recon,
    int n,
    float* __restrict__ out)
{
    int i = blockIdx.x * blockDim.x + threadIdx.x;

    if (i < n) {
        int p = pid[i];
        int r = recon[i];
        // noise (pid==0) and non-reconstructable hits go to the dropped
        // segment 0 in the reference -> contribute nothing here. Predicate
        // BEFORE touching pred/tp (saves ~25% of 32B sectors).
        if (r > 0 && p != 0) {
            float  b = beta[i];
            float4 q = pred[i];
            float4 t = tp[i];

            float a  = atanhf(b);
            float xi = a * a;

            float dx = q.x - t.x;
            float dy = q.y - t.y;
            float dz = q.z - t.z;
            float dw = q.w - t.w;
            float mse = dx * dx + dy * dy + dz * dz + dw * dw;

            atomicAdd(&g_acc.num[p], mse * xi);
            atomicAdd(&g_acc.den[p], xi);
        }
    }

    // ---- last-block reduction (threadfence ticket pattern) ----
    __threadfence();
    __syncthreads();

    __shared__ unsigned int s_last;
    if (threadIdx.x == 0)
        s_last = (atomicAdd(&g_acc.ticket, 1u) == gridDim.x - 1u) ? 1u : 0u;
    __syncthreads();
    if (!s_last) return;

    // All other blocks' atomics are visible (they fenced before the ticket).
    // num/den are hot in L2 (written by L2 atomics) -> __ldcg.
    double v = 0.0;
    #pragma unroll 4
    for (int p = 1 + (int)threadIdx.x; p < P_SEGS; p += TPB) {
        float nu = __ldcg(&g_acc.num[p]);
        float de = __ldcg(&g_acc.den[p]);
        v += (double)(nu / de);   // ratio in f32, like the reference; sum in f64
    }

    // block reduce (32 warps)
    #pragma unroll
    for (int off = 16; off > 0; off >>= 1)
        v += __shfl_down_sync(0xffffffffu, v, off);

    __shared__ double warp_sums[TPB / 32];
    int lane = threadIdx.x & 31;
    int wid  = threadIdx.x >> 5;
    if (lane == 0) warp_sums[wid] = v;
    __syncthreads();

    if (wid == 0) {
        v = (lane < TPB / 32) ? warp_sums[lane] : 0.0;
        #pragma unroll
        for (int off = 16; off > 0; off >>= 1)
            v += __shfl_down_sync(0xffffffffu, v, off);
        if (lane == 0)
            *out = (float)(v / (double)(P_SEGS - 1));
    }
}

extern "C" void kernel_launch(void* const* d_in, const int* in_sizes, int n_in,
                              void* d_out, int out_size) {
    const float* beta  = (const float*)d_in[0];
    const float* pred  = (const float*)d_in[1];
    const int*   pid   = (const int*)d_in[2];
    const float* tp    = (const float*)d_in[3];
    const int*   recon = (const int*)d_in[4];
    int n = in_sizes[0];

    void* acc_ptr = nullptr;
    cudaGetSymbolAddress(&acc_ptr, g_acc);
    cudaMemsetAsync(acc_ptr, 0, sizeof(Acc), 0);

    int grid = (n + TPB - 1) / TPB;
    fused_kernel<<<grid, TPB>>>(
        beta, (const float4*)pred, pid, (const float4*)tp, recon, n,
        (float*)d_out);
}